// round 16
// baseline (speedup 1.0000x reference)
#include <cuda_runtime.h>
#include <cstdint>

#define BB 64
#define HH 1024
#define SS 2048
#define LL 15

// ---------------- scratch (static device globals; no allocation) ------------
__device__ __align__(16) float g_T[3 * BB * HH];   // tanh feats [seg][b][h]
__device__ __align__(16) float g_M2[HH * LL];      // W2 @ Wout
__device__ __align__(16) float g_M3[3 * HH * LL];  // W1 @ M2
__device__ __align__(16) float g_M4[3 * HH * LL];  // BD @ M3
__device__ float g_c[LL];                          // collapsed bias

// ---------------- prep: span means + tanh -> g_T fp32 -----------------------
__global__ void prep_kernel(const float* __restrict__ x,
                            const int* __restrict__ eidx) {
    int b = blockIdx.x;
    int h = blockIdx.y * 256 + threadIdx.x;

    int s1 = eidx[b * 4 + 0], e1 = eidx[b * 4 + 1];
    int s2 = eidx[b * 4 + 2], e2 = eidx[b * 4 + 3];
    float c1 = 1.0f / (float)max(e1 - s1, 1);
    float c2 = 1.0f / (float)max(e2 - s2, 1);
    const float* xb = x + (size_t)b * SS * HH;

    float a1 = 0.f;
#pragma unroll 4
    for (int p = s1; p < e1; ++p) a1 += xb[(size_t)p * HH + h];
    float a2 = 0.f;
#pragma unroll 4
    for (int p = s2; p < e2; ++p) a2 += xb[(size_t)p * HH + h];

    g_T[(size_t)(0 * BB + b) * HH + h] = tanhf(xb[h]);
    g_T[(size_t)(1 * BB + b) * HH + h] = tanhf(a1 * c1);
    g_T[(size_t)(2 * BB + b) * HH + h] = tanhf(a2 * c2);
}

// ---------------- rowdot: out[j][l] = sum_k A_j[k] * B[k][l] -----------------
// K = 1024, N = 15. B ([1024][15], per-segment) transposed into smem [15][1024].
// 256 threads, 16 rows/block (2 per warp, full-row register prefetch).
// bsel: 0 = Wout, 1 = g_M2, 2 = g_M3 (+seg offset). osel: 0=g_M2 1=g_M3 2=g_M4.
// seg_mode: rows segmented by 1024 across A0/A1/A2.
// cflag: block nrow_blocks computes collapsed bias g_c instead of rows.
__global__ __launch_bounds__(256)
void rowdot(const float* __restrict__ A0p, const float* __restrict__ A1p,
            const float* __restrict__ A2p,
            int bsel, int osel, int seg_mode, int nrow_blocks, int cflag,
            const float* __restrict__ bcls, const float* __restrict__ be1,
            const float* __restrict__ be2, const float* __restrict__ b1,
            const float* __restrict__ b2,  const float* __restrict__ bout,
            const float* __restrict__ Wout) {
    extern __shared__ float Bs[];   // 15*1024 floats (61440 B)
    int t = threadIdx.x;

    if (cflag && blockIdx.x == (unsigned)nrow_blocks) {
        // ---- collapsed-bias block: c = bcat@M3 + b1@M2 + b2@Wout + bout ----
        float acc[LL];
#pragma unroll
        for (int l = 0; l < LL; l++) acc[l] = 0.f;
        for (int j = t; j < 3 * HH; j += 256) {
            int s = j >> 10, h = j & (HH - 1);
            float bc = (s == 0 ? bcls : (s == 1 ? be1 : be2))[h];
            const float* m = g_M3 + (size_t)j * LL;
#pragma unroll
            for (int l = 0; l < LL; l++) acc[l] += bc * m[l];
        }
        for (int i = t; i < HH; i += 256) {
            float v1 = b1[i], v2 = b2[i];
            const float* m2 = g_M2 + (size_t)i * LL;
            const float* wo = Wout + (size_t)i * LL;
#pragma unroll
            for (int l = 0; l < LL; l++) acc[l] += v1 * m2[l] + v2 * wo[l];
        }
        float* S = Bs;   // reuse smem: [256][16]
#pragma unroll
        for (int l = 0; l < LL; l++) S[t * 16 + l] = acc[l];
        __syncthreads();
        if (t < LL) {
            float s = bout[t];
            for (int i = 0; i < 256; i++) s += S[i * 16 + t];
            g_c[t] = s;
        }
        return;
    }

    // ---- row blocks ----
    int jblk = blockIdx.x * 16;
    int seg = seg_mode ? (jblk >> 10) : 0;
    const float* A = seg_mode ? (seg == 0 ? A0p : (seg == 1 ? A1p : A2p)) : A0p;
    const float* Bsrc = (bsel == 0) ? Wout : (bsel == 1 ? g_M2 : g_M3);
    const float* Bp = Bsrc + (seg_mode ? (size_t)seg * HH * LL : 0);
    float* outp = (osel == 0) ? g_M2 : (osel == 1 ? g_M3 : g_M4);

    // load + transpose B into smem (coalesced global reads)
    for (int idx = t; idx < HH * LL; idx += 256) {
        int k = idx / LL, l = idx - k * LL;
        Bs[l * HH + k] = Bp[idx];
    }
    __syncthreads();

    int warp = t >> 5, lane = t & 31;
    int jloc = (seg_mode ? (jblk & (HH - 1)) : jblk) + warp * 2;

    const float4* Ar0 = (const float4*)(A + (size_t)jloc * HH);
    const float4* Ar1 = (const float4*)(A + (size_t)(jloc + 1) * HH);
    float4 a0[8], a1[8];
#pragma unroll
    for (int i = 0; i < 8; i++) a0[i] = __ldg(&Ar0[lane + 32 * i]);
#pragma unroll
    for (int i = 0; i < 8; i++) a1[i] = __ldg(&Ar1[lane + 32 * i]);

    float acc0[LL], acc1[LL];
#pragma unroll
    for (int l = 0; l < LL; l++) { acc0[l] = 0.f; acc1[l] = 0.f; }

    const float4* Bs4 = (const float4*)Bs;
#pragma unroll
    for (int i = 0; i < 8; i++) {
        int o = lane + 32 * i;
#pragma unroll
        for (int l = 0; l < LL; l++) {
            float4 bv = Bs4[l * 256 + o];
            acc0[l] += a0[i].x * bv.x + a0[i].y * bv.y + a0[i].z * bv.z + a0[i].w * bv.w;
            acc1[l] += a1[i].x * bv.x + a1[i].y * bv.y + a1[i].z * bv.z + a1[i].w * bv.w;
        }
    }

#pragma unroll
    for (int l = 0; l < LL; l++) {
#pragma unroll
        for (int o = 16; o; o >>= 1) {
            acc0[l] += __shfl_down_sync(0xffffffffu, acc0[l], o);
            acc1[l] += __shfl_down_sync(0xffffffffu, acc1[l], o);
        }
    }
    if (lane == 0) {
        int jg = jblk + warp * 2;
        float* o0 = outp + (size_t)jg * LL;
#pragma unroll
        for (int l = 0; l < LL; l++) o0[l] = acc0[l];
#pragma unroll
        for (int l = 0; l < LL; l++) o0[LL + l] = acc1[l];
    }
}

// ---------------- final: out[b][l] = T[b] . M4[:,l] + c[l] -------------------
__global__ __launch_bounds__(128)
void final_gemm(float* __restrict__ out) {
    int b = blockIdx.x;   // 0..63
    int t = threadIdx.x;  // 128
    float acc[LL];
#pragma unroll
    for (int l = 0; l < LL; l++) acc[l] = 0.f;
    for (int j = t; j < 3 * HH; j += 128) {
        int s = j >> 10, h = j & (HH - 1);
        float tv = g_T[(size_t)(s * BB + b) * HH + h];
        const float* m = g_M4 + (size_t)j * LL;
#pragma unroll
        for (int l = 0; l < LL; l++) acc[l] += tv * m[l];
    }
    __shared__ float S[128][16];
#pragma unroll
    for (int l = 0; l < LL; l++) S[t][l] = acc[l];
    __syncthreads();
    if (t < LL) {
        float s = g_c[t];
#pragma unroll 8
        for (int i = 0; i < 128; i++) s += S[i][t];
        out[b * LL + t] = s;
    }
}

// ---------------- launch ------------------------------------------------------
extern "C" void kernel_launch(void* const* d_in, const int* in_sizes, int n_in,
                              void* d_out, int out_size) {
    const float* x      = (const float*)d_in[0];
    const int*   eidx   = (const int*)d_in[1];
    const float* W_cls  = (const float*)d_in[2];
    const float* b_cls  = (const float*)d_in[3];
    const float* W_e1   = (const float*)d_in[4];
    const float* b_e1   = (const float*)d_in[5];
    const float* W_e2   = (const float*)d_in[6];
    const float* b_e2   = (const float*)d_in[7];
    const float* W1     = (const float*)d_in[8];
    const float* b1     = (const float*)d_in[9];
    const float* W2     = (const float*)d_in[10];
    const float* b2     = (const float*)d_in[11];
    const float* Wout   = (const float*)d_in[12];
    const float* bout   = (const float*)d_in[13];
    float* out = (float*)d_out;

    const int RSMEM = HH * LL * sizeof(float);   // 61440 B
    cudaFuncSetAttribute(rowdot, cudaFuncAttributeMaxDynamicSharedMemorySize,
                         RSMEM);

    // 1) tanh features (independent of weight collapse)
    prep_kernel<<<dim3(BB, HH / 256), 256>>>(x, eidx);

    // 2) M2 = W2 @ Wout   [1024 x 15]
    rowdot<<<HH / 16, 256, RSMEM>>>(W2, nullptr, nullptr,
                                    0 /*B=Wout*/, 0 /*out=M2*/, 0, HH / 16, 0,
                                    nullptr, nullptr, nullptr, nullptr,
                                    nullptr, nullptr, Wout);

    // 3) M3 = W1 @ M2     [3072 x 15]
    rowdot<<<3 * HH / 16, 256, RSMEM>>>(W1, nullptr, nullptr,
                                        1 /*B=M2*/, 1 /*out=M3*/, 0, 3 * HH / 16, 0,
                                        nullptr, nullptr, nullptr, nullptr,
                                        nullptr, nullptr, Wout);

    // 4) M4 = BD @ M3 (segmented) + collapsed bias c (extra block)
    rowdot<<<3 * HH / 16 + 1, 256, RSMEM>>>(W_cls, W_e1, W_e2,
                                            2 /*B=M3*/, 2 /*out=M4*/, 1,
                                            3 * HH / 16, 1,
                                            b_cls, b_e1, b_e2, b1, b2, bout,
                                            Wout);

    // 5) out = T @ M4 + c
    final_gemm<<<BB, 128>>>(out);

    (void)in_sizes; (void)n_in; (void)out_size;
}

// round 17
// speedup vs baseline: 1.0303x; 1.0303x over previous
#include <cuda_runtime.h>
#include <cstdint>

#define BB 64
#define HH 1024
#define SS 2048
#define LL 15

// ---------------- scratch (static device globals; no allocation) ------------
__device__ __align__(16) float g_T[3 * BB * HH];    // tanh feats [seg][b][h]
__device__ __align__(16) float g_WoT[16 * HH];      // Wout^T padded [16][1024]
__device__ __align__(16) float g_M2T[16 * HH];      // (W2@Wout)^T  [16][1024]
__device__ __align__(16) float g_M3T[3 * 16 * HH];  // (W1@M2)^T    [3][16][1024]
__device__ __align__(16) float g_M4T[3 * 16 * HH];  // (BD@M3)^T    [3][16][1024]
__device__ float g_c[LL];                           // collapsed bias

// ---------------- prep: span means + tanh -> g_T fp32 -----------------------
__global__ void prep_kernel(const float* __restrict__ x,
                            const int* __restrict__ eidx) {
    int b = blockIdx.x;
    int h = blockIdx.y * 256 + threadIdx.x;

    int s1 = eidx[b * 4 + 0], e1 = eidx[b * 4 + 1];
    int s2 = eidx[b * 4 + 2], e2 = eidx[b * 4 + 3];
    float c1 = 1.0f / (float)max(e1 - s1, 1);
    float c2 = 1.0f / (float)max(e2 - s2, 1);
    const float* xb = x + (size_t)b * SS * HH;

    float a1 = 0.f;
#pragma unroll 4
    for (int p = s1; p < e1; ++p) a1 += xb[(size_t)p * HH + h];
    float a2 = 0.f;
#pragma unroll 4
    for (int p = s2; p < e2; ++p) a2 += xb[(size_t)p * HH + h];

    g_T[(size_t)(0 * BB + b) * HH + h] = tanhf(xb[h]);
    g_T[(size_t)(1 * BB + b) * HH + h] = tanhf(a1 * c1);
    g_T[(size_t)(2 * BB + b) * HH + h] = tanhf(a2 * c2);
}

// ---------------- Wout transpose: [1024][15] -> WoT [16][1024] ---------------
__global__ __launch_bounds__(256)
void transW(const float* __restrict__ Wout) {
    int k = blockIdx.x * 256 + threadIdx.x;   // 0..1023
    const float* wr = Wout + (size_t)k * LL;
#pragma unroll
    for (int l = 0; l < LL; l++)
        g_WoT[l * HH + k] = wr[l];
}

// ---------------- rowdot: outT[l][j] = A_j . BT[l] ---------------------------
// K = 1024, N = 15. BT ([16][1024] per segment) copied straight into smem.
// 256 threads, 16 rows/block (2 per warp). A rows prefetched before B copy.
// bsel: 0=WoT 1=M2T 2=M3T(+seg). osel: 0=M2T 1=M3T 2=M4T (seg from global row).
// cflag: block nrow_blocks computes collapsed bias g_c instead.
__global__ __launch_bounds__(256)
void rowdot(const float* __restrict__ A0p, const float* __restrict__ A1p,
            const float* __restrict__ A2p,
            int bsel, int osel, int seg_mode, int nrow_blocks, int cflag,
            const float* __restrict__ bcls, const float* __restrict__ be1,
            const float* __restrict__ be2, const float* __restrict__ b1,
            const float* __restrict__ b2,  const float* __restrict__ bout) {
    extern __shared__ float Bs[];   // 16*1024 floats (65536 B)
    int t = threadIdx.x;

    if (cflag && blockIdx.x == (unsigned)nrow_blocks) {
        // ---- collapsed bias: c = bcat@M3 + b1@M2 + b2@Wout + bout ----------
        float acc[LL];
#pragma unroll
        for (int l = 0; l < LL; l++) acc[l] = 0.f;
        for (int j = t; j < 3 * HH; j += 256) {
            int s = j >> 10, h = j & (HH - 1);
            float bc = (s == 0 ? bcls : (s == 1 ? be1 : be2))[h];
#pragma unroll
            for (int l = 0; l < LL; l++)
                acc[l] += bc * g_M3T[(size_t)(s * 16 + l) * HH + h];
        }
        for (int i = t; i < HH; i += 256) {
            float v1 = b1[i], v2 = b2[i];
#pragma unroll
            for (int l = 0; l < LL; l++)
                acc[l] += v1 * g_M2T[(size_t)l * HH + i]
                        + v2 * g_WoT[(size_t)l * HH + i];
        }
#pragma unroll
        for (int l = 0; l < LL; l++) Bs[t * 16 + l] = acc[l];
        __syncthreads();
        if (t < LL) {
            float s = bout[t];
            for (int i = 0; i < 256; i++) s += Bs[i * 16 + t];
            g_c[t] = s;
        }
        return;
    }

    int jblk = blockIdx.x * 16;
    int warp = t >> 5, lane = t & 31;
    int jg = jblk + warp * 2;                 // global row pair
    int aseg = seg_mode ? (jg >> 10) : 0;
    int aloc = seg_mode ? (jg & (HH - 1)) : jg;
    const float* A = seg_mode ? (aseg == 0 ? A0p : (aseg == 1 ? A1p : A2p)) : A0p;

    // ---- A prefetch (in flight during B copy + barrier) ----
    const float4* Ar0 = (const float4*)(A + (size_t)aloc * HH);
    const float4* Ar1 = (const float4*)(A + (size_t)(aloc + 1) * HH);
    float4 a0[8], a1[8];
#pragma unroll
    for (int i = 0; i < 8; i++) a0[i] = __ldg(&Ar0[lane + 32 * i]);
#pragma unroll
    for (int i = 0; i < 8; i++) a1[i] = __ldg(&Ar1[lane + 32 * i]);

    // ---- B copy: straight float4, coalesced, conflict-free ----
    {
        int bseg = seg_mode ? (jblk >> 10) : 0;
        const float* Bsrc = (bsel == 0) ? g_WoT : (bsel == 1 ? g_M2T : g_M3T);
        const float4* Bp4 = (const float4*)(Bsrc + (size_t)bseg * 16 * HH);
        float4* Bs4w = (float4*)Bs;
#pragma unroll
        for (int i = 0; i < 16; i++)          // 16 rows x 1024 floats = 4096 f4
            Bs4w[t + 256 * i] = Bp4[t + 256 * i];
    }
    __syncthreads();

    // ---- compute ----
    float acc0[LL], acc1[LL];
#pragma unroll
    for (int l = 0; l < LL; l++) { acc0[l] = 0.f; acc1[l] = 0.f; }

    const float4* Bs4 = (const float4*)Bs;
#pragma unroll
    for (int i = 0; i < 8; i++) {
        int o = lane + 32 * i;
#pragma unroll
        for (int l = 0; l < LL; l++) {
            float4 bv = Bs4[l * 256 + o];
            acc0[l] += a0[i].x * bv.x + a0[i].y * bv.y + a0[i].z * bv.z + a0[i].w * bv.w;
            acc1[l] += a1[i].x * bv.x + a1[i].y * bv.y + a1[i].z * bv.z + a1[i].w * bv.w;
        }
    }

#pragma unroll
    for (int l = 0; l < LL; l++) {
#pragma unroll
        for (int o = 16; o; o >>= 1) {
            acc0[l] += __shfl_down_sync(0xffffffffu, acc0[l], o);
            acc1[l] += __shfl_down_sync(0xffffffffu, acc1[l], o);
        }
    }
    if (lane == 0) {
        float* outp = (osel == 0) ? g_M2T : (osel == 1 ? g_M3T : g_M4T);
        int oseg = jg >> 10, oloc = jg & (HH - 1);
        float* orow = outp + (size_t)oseg * 16 * HH + oloc;
#pragma unroll
        for (int l = 0; l < LL; l++) orow[(size_t)l * HH]     = acc0[l];
#pragma unroll
        for (int l = 0; l < LL; l++) orow[(size_t)l * HH + 1] = acc1[l];
    }
}

// ---------------- final: out[b][l] = T[b] . M4T[l] + c[l] --------------------
__global__ __launch_bounds__(128)
void final_gemm(float* __restrict__ out) {
    int b = blockIdx.x;   // 0..63
    int t = threadIdx.x;  // 128
    float acc[LL];
#pragma unroll
    for (int l = 0; l < LL; l++) acc[l] = 0.f;
    for (int j = t; j < 3 * HH; j += 128) {
        int s = j >> 10, h = j & (HH - 1);
        float tv = g_T[(size_t)(s * BB + b) * HH + h];
#pragma unroll
        for (int l = 0; l < LL; l++)
            acc[l] += tv * g_M4T[(size_t)(s * 16 + l) * HH + h];
    }
    __shared__ float S[128][16];
#pragma unroll
    for (int l = 0; l < LL; l++) S[t][l] = acc[l];
    __syncthreads();
    if (t < LL) {
        float s = g_c[t];
#pragma unroll 8
        for (int i = 0; i < 128; i++) s += S[i][t];
        out[b * LL + t] = s;
    }
}

// ---------------- launch ------------------------------------------------------
extern "C" void kernel_launch(void* const* d_in, const int* in_sizes, int n_in,
                              void* d_out, int out_size) {
    const float* x      = (const float*)d_in[0];
    const int*   eidx   = (const int*)d_in[1];
    const float* W_cls  = (const float*)d_in[2];
    const float* b_cls  = (const float*)d_in[3];
    const float* W_e1   = (const float*)d_in[4];
    const float* b_e1   = (const float*)d_in[5];
    const float* W_e2   = (const float*)d_in[6];
    const float* b_e2   = (const float*)d_in[7];
    const float* W1     = (const float*)d_in[8];
    const float* b1     = (const float*)d_in[9];
    const float* W2     = (const float*)d_in[10];
    const float* b2     = (const float*)d_in[11];
    const float* Wout   = (const float*)d_in[12];
    const float* bout   = (const float*)d_in[13];
    float* out = (float*)d_out;

    const int RSMEM = 16 * HH * sizeof(float);   // 65536 B
    cudaFuncSetAttribute(rowdot, cudaFuncAttributeMaxDynamicSharedMemorySize,
                         RSMEM);

    // 1) tanh features + Wout transpose
    prep_kernel<<<dim3(BB, HH / 256), 256>>>(x, eidx);
    transW<<<HH / 256, 256>>>(Wout);

    // 2) M2T = (W2 @ Wout)^T
    rowdot<<<HH / 16, 256, RSMEM>>>(W2, nullptr, nullptr,
                                    0, 0, 0, HH / 16, 0,
                                    nullptr, nullptr, nullptr,
                                    nullptr, nullptr, nullptr);

    // 3) M3T = (W1 @ M2)^T
    rowdot<<<3 * HH / 16, 256, RSMEM>>>(W1, nullptr, nullptr,
                                        1, 1, 0, 3 * HH / 16, 0,
                                        nullptr, nullptr, nullptr,
                                        nullptr, nullptr, nullptr);

    // 4) M4T = (BD @ M3)^T + collapsed bias (extra block)
    rowdot<<<3 * HH / 16 + 1, 256, RSMEM>>>(W_cls, W_e1, W_e2,
                                            2, 2, 1, 3 * HH / 16, 1,
                                            b_cls, b_e1, b_e2, b1, b2, bout);

    // 5) out = T @ M4 + c
    final_gemm<<<BB, 128>>>(out);

    (void)in_sizes; (void)n_in; (void)out_size;
}